// round 3
// baseline (speedup 1.0000x reference)
#include <cuda_runtime.h>
#include <cuda_bf16.h>

// Snack: out[p] = tanh((f[i]-f[j])^T M (f[i]-f[j])), P = 8,388,608, 20 AAs.
// Single fused persistent kernel:
//   - each CTA builds the 400-entry tanh table in smem (rolled loops, low regs)
//   - then a grid-stride, ILP-4, 128-bit gather (bandwidth bound)
// Traffic floor: 12 B/pair = 100.7 MB -> ~13-14us achievable.

#define NUM_AA   20
#define FEAT_DIM 16
#define TBL      (NUM_AA * NUM_AA)
#define THREADS  256
#define ILP      4

__global__ __launch_bounds__(THREADS) void snack_fused_kernel(
    const float*  __restrict__ features,   // [20, 16]
    const float*  __restrict__ M,          // [16, 16]
    const int4*   __restrict__ idx_i4,     // [P/4]
    const int4*   __restrict__ idx_j4,     // [P/4]
    float4*       __restrict__ out4,       // [P/4]
    int n4)
{
    __shared__ float s_feat[NUM_AA * FEAT_DIM];
    __shared__ float s_M[FEAT_DIM * FEAT_DIM];
    __shared__ float s_tbl[TBL];

    const int t = threadIdx.x;

    for (int k = t; k < NUM_AA * FEAT_DIM; k += THREADS) s_feat[k] = features[k];
    for (int k = t; k < FEAT_DIM * FEAT_DIM; k += THREADS) s_M[k] = M[k];
    __syncthreads();

    // Build table with ROLLED loops + recompute-from-smem so the register
    // footprint of this one-time section never exceeds the gather loop's.
    for (int e = t; e < TBL; e += THREADS) {
        const int i = e / NUM_AA;
        const int j = e % NUM_AA;
        const float* fi = &s_feat[i * FEAT_DIM];
        const float* fj = &s_feat[j * FEAT_DIM];
        float dist = 0.0f;
#pragma unroll 1
        for (int x = 0; x < FEAT_DIM; x++) {
            float mv0 = 0.0f, mv1 = 0.0f;
#pragma unroll 1
            for (int y = 0; y < FEAT_DIM; y += 2) {
                mv0 = fmaf(s_M[x * FEAT_DIM + y],     fi[y]   - fj[y],   mv0);
                mv1 = fmaf(s_M[x * FEAT_DIM + y + 1], fi[y+1] - fj[y+1], mv1);
            }
            dist = fmaf(fi[x] - fj[x], mv0 + mv1, dist);
        }
        s_tbl[e] = tanhf(dist);
    }
    __syncthreads();

    // Persistent grid-stride gather with 4 independent 128-bit lanes in flight.
    const int stride = gridDim.x * THREADS;
    int p = blockIdx.x * THREADS + t;

    for (; p + 3 * stride < n4; p += 4 * stride) {
        int4 a0 = idx_i4[p];
        int4 a1 = idx_i4[p + stride];
        int4 a2 = idx_i4[p + 2 * stride];
        int4 a3 = idx_i4[p + 3 * stride];
        int4 b0 = idx_j4[p];
        int4 b1 = idx_j4[p + stride];
        int4 b2 = idx_j4[p + 2 * stride];
        int4 b3 = idx_j4[p + 3 * stride];
        float4 o;
        o.x = s_tbl[a0.x * NUM_AA + b0.x];
        o.y = s_tbl[a0.y * NUM_AA + b0.y];
        o.z = s_tbl[a0.z * NUM_AA + b0.z];
        o.w = s_tbl[a0.w * NUM_AA + b0.w];
        out4[p] = o;
        o.x = s_tbl[a1.x * NUM_AA + b1.x];
        o.y = s_tbl[a1.y * NUM_AA + b1.y];
        o.z = s_tbl[a1.z * NUM_AA + b1.z];
        o.w = s_tbl[a1.w * NUM_AA + b1.w];
        out4[p + stride] = o;
        o.x = s_tbl[a2.x * NUM_AA + b2.x];
        o.y = s_tbl[a2.y * NUM_AA + b2.y];
        o.z = s_tbl[a2.z * NUM_AA + b2.z];
        o.w = s_tbl[a2.w * NUM_AA + b2.w];
        out4[p + 2 * stride] = o;
        o.x = s_tbl[a3.x * NUM_AA + b3.x];
        o.y = s_tbl[a3.y * NUM_AA + b3.y];
        o.z = s_tbl[a3.z * NUM_AA + b3.z];
        o.w = s_tbl[a3.w * NUM_AA + b3.w];
        out4[p + 3 * stride] = o;
    }
    // Tail
    for (; p < n4; p += stride) {
        int4 a = idx_i4[p];
        int4 b = idx_j4[p];
        float4 o;
        o.x = s_tbl[a.x * NUM_AA + b.x];
        o.y = s_tbl[a.y * NUM_AA + b.y];
        o.z = s_tbl[a.z * NUM_AA + b.z];
        o.w = s_tbl[a.w * NUM_AA + b.w];
        out4[p] = o;
    }
}

extern "C" void kernel_launch(void* const* d_in, const int* in_sizes, int n_in,
                              void* d_out, int out_size)
{
    const float* features = (const float*)d_in[0];   // [20,16]
    const float* M        = (const float*)d_in[1];   // [16,16]
    const int*   idx_i    = (const int*)d_in[2];     // [P]
    const int*   idx_j    = (const int*)d_in[3];     // [P]
    float*       out      = (float*)d_out;           // [P]

    const int P  = out_size;   // 8,388,608
    const int n4 = P / 4;      // 2,097,152

    // Persistent single-wave grid: exactly the number of CTAs that fit.
    static int blocks = 0;
    if (blocks == 0) {
        int per_sm = 0;
        cudaOccupancyMaxActiveBlocksPerMultiprocessor(
            &per_sm, snack_fused_kernel, THREADS, 0);
        if (per_sm < 1) per_sm = 1;
        int sms = 0;
        cudaDeviceGetAttribute(&sms, cudaDevAttrMultiProcessorCount, 0);
        if (sms <= 0) sms = 148;
        blocks = per_sm * sms;
        int max_blocks = (n4 + THREADS - 1) / THREADS;
        if (blocks > max_blocks) blocks = max_blocks;
    }

    snack_fused_kernel<<<blocks, THREADS>>>(
        features, M,
        (const int4*)idx_i, (const int4*)idx_j,
        (float4*)out, n4);
}

// round 4
// speedup vs baseline: 5.1865x; 5.1865x over previous
#include <cuda_runtime.h>
#include <cuda_bf16.h>

// Snack: out[p] = tanh((f[i]-f[j])^T M (f[i]-f[j])), P = 8,388,608, 20 AAs.
// Fused persistent kernel:
//   - per-CTA 400-entry table build in REGISTERS (d[16] unrolled over y,
//     rolled over x; M read as warp-uniform smem broadcast; features via
//     __ldg L1 hits). ~1us, no LDS conflicts, ~30 regs.
//   - grid-stride ILP-4 128-bit gather (bandwidth bound).
// Traffic floor: 12 B/pair = 100.7 MB -> ~14us practical.

#define NUM_AA   20
#define FEAT_DIM 16
#define TBL      (NUM_AA * NUM_AA)
#define THREADS  256

__global__ __launch_bounds__(THREADS) void snack_fused_kernel(
    const float*  __restrict__ features,   // [20, 16]
    const float*  __restrict__ M,          // [16, 16]
    const int4*   __restrict__ idx_i4,     // [P/4]
    const int4*   __restrict__ idx_j4,     // [P/4]
    float4*       __restrict__ out4,       // [P/4]
    int n4)
{
    __shared__ float s_M[FEAT_DIM * FEAT_DIM];
    __shared__ float s_tbl[TBL];

    const int t = threadIdx.x;

    for (int k = t; k < FEAT_DIM * FEAT_DIM; k += THREADS) s_M[k] = M[k];
    __syncthreads();

    // Register-resident table build: d[] in regs (y fully unrolled),
    // x rolled to bound register pressure. M reads are warp-uniform
    // smem broadcasts (1 phase, no conflicts).
    for (int e = t; e < TBL; e += THREADS) {
        const int i = e / NUM_AA;
        const int j = e % NUM_AA;
        float d[FEAT_DIM];
#pragma unroll
        for (int x = 0; x < FEAT_DIM; x++)
            d[x] = __ldg(&features[i * FEAT_DIM + x]) -
                   __ldg(&features[j * FEAT_DIM + x]);
        float dist = 0.0f;
#pragma unroll 1
        for (int x = 0; x < FEAT_DIM; x++) {
            float mv = 0.0f;
#pragma unroll
            for (int y = 0; y < FEAT_DIM; y++)
                mv = fmaf(s_M[x * FEAT_DIM + y], d[y], mv);
            dist = fmaf(d[x], mv, dist);
        }
        s_tbl[e] = tanhf(dist);
    }
    __syncthreads();

    // Persistent grid-stride gather, 4 independent 128-bit lanes in flight.
    const int stride = gridDim.x * THREADS;
    int p = blockIdx.x * THREADS + t;

    for (; p + 3 * stride < n4; p += 4 * stride) {
        int4 a0 = idx_i4[p];
        int4 a1 = idx_i4[p + stride];
        int4 a2 = idx_i4[p + 2 * stride];
        int4 a3 = idx_i4[p + 3 * stride];
        int4 b0 = idx_j4[p];
        int4 b1 = idx_j4[p + stride];
        int4 b2 = idx_j4[p + 2 * stride];
        int4 b3 = idx_j4[p + 3 * stride];
        float4 o;
        o.x = s_tbl[a0.x * NUM_AA + b0.x];
        o.y = s_tbl[a0.y * NUM_AA + b0.y];
        o.z = s_tbl[a0.z * NUM_AA + b0.z];
        o.w = s_tbl[a0.w * NUM_AA + b0.w];
        out4[p] = o;
        o.x = s_tbl[a1.x * NUM_AA + b1.x];
        o.y = s_tbl[a1.y * NUM_AA + b1.y];
        o.z = s_tbl[a1.z * NUM_AA + b1.z];
        o.w = s_tbl[a1.w * NUM_AA + b1.w];
        out4[p + stride] = o;
        o.x = s_tbl[a2.x * NUM_AA + b2.x];
        o.y = s_tbl[a2.y * NUM_AA + b2.y];
        o.z = s_tbl[a2.z * NUM_AA + b2.z];
        o.w = s_tbl[a2.w * NUM_AA + b2.w];
        out4[p + 2 * stride] = o;
        o.x = s_tbl[a3.x * NUM_AA + b3.x];
        o.y = s_tbl[a3.y * NUM_AA + b3.y];
        o.z = s_tbl[a3.z * NUM_AA + b3.z];
        o.w = s_tbl[a3.w * NUM_AA + b3.w];
        out4[p + 3 * stride] = o;
    }
    for (; p < n4; p += stride) {
        int4 a = idx_i4[p];
        int4 b = idx_j4[p];
        float4 o;
        o.x = s_tbl[a.x * NUM_AA + b.x];
        o.y = s_tbl[a.y * NUM_AA + b.y];
        o.z = s_tbl[a.z * NUM_AA + b.z];
        o.w = s_tbl[a.w * NUM_AA + b.w];
        out4[p] = o;
    }
}

extern "C" void kernel_launch(void* const* d_in, const int* in_sizes, int n_in,
                              void* d_out, int out_size)
{
    const float* features = (const float*)d_in[0];   // [20,16]
    const float* M        = (const float*)d_in[1];   // [16,16]
    const int*   idx_i    = (const int*)d_in[2];     // [P]
    const int*   idx_j    = (const int*)d_in[3];     // [P]
    float*       out      = (float*)d_out;           // [P]

    const int P  = out_size;   // 8,388,608
    const int n4 = P / 4;      // 2,097,152

    // Persistent single-wave grid.
    static int blocks = 0;
    if (blocks == 0) {
        int per_sm = 0;
        cudaOccupancyMaxActiveBlocksPerMultiprocessor(
            &per_sm, snack_fused_kernel, THREADS, 0);
        if (per_sm < 1) per_sm = 1;
        int sms = 0;
        cudaDeviceGetAttribute(&sms, cudaDevAttrMultiProcessorCount, 0);
        if (sms <= 0) sms = 148;
        blocks = per_sm * sms;
        int max_blocks = (n4 + THREADS - 1) / THREADS;
        if (blocks > max_blocks) blocks = max_blocks;
    }

    snack_fused_kernel<<<blocks, THREADS>>>(
        features, M,
        (const int4*)idx_i, (const int4*)idx_j,
        (float4*)out, n4);
}

// round 6
// speedup vs baseline: 7.4332x; 1.4332x over previous
#include <cuda_runtime.h>
#include <cuda_bf16.h>

// Snack: out[p] = tanh((f[i]-f[j])^T M (f[i]-f[j])), P = 8,388,608, 20 AAs.
// Fused persistent kernel with FACTORIZED table build:
//   G = (F M) F^T  (20x20);  dist(i,j) = G[ii] - G[ij] - G[ji] + G[jj]
//   -> ~31K FMA per CTA instead of ~109K, no big register arrays.
// Then a grid-stride ILP-4 128-bit gather (bandwidth bound).
// Traffic floor: 12 B/pair = 100.7 MB -> ~13-14us practical.

#define NUM_AA   20
#define FEAT_DIM 16
#define FPAD     17          // stride-17 padding: odd stride => conflict-free
#define TBL      (NUM_AA * NUM_AA)
#define THREADS  256
#define NF       (NUM_AA * FEAT_DIM)   // 320

__global__ __launch_bounds__(THREADS, 5) void snack_fused_kernel(
    const float*  __restrict__ features,   // [20, 16]
    const float*  __restrict__ M,          // [16, 16]
    const int4*   __restrict__ idx_i4,     // [P/4]
    const int4*   __restrict__ idx_j4,     // [P/4]
    float4*       __restrict__ out4,       // [P/4]
    int n4)
{
    __shared__ float s_F[NUM_AA * FPAD];    // features, padded rows
    __shared__ float s_M[FEAT_DIM * FEAT_DIM];
    __shared__ float s_FM[NUM_AA * FPAD];   // F @ M, padded rows
    __shared__ float s_tbl[TBL];

    const int t = threadIdx.x;

    // Stage F (padded) and M — STRIDED: 320 > THREADS.
    for (int k = t; k < NF; k += THREADS) {
        const int r = k >> 4, c = k & 15;
        s_F[r * FPAD + c] = features[k];
    }
    for (int k = t; k < FEAT_DIM * FEAT_DIM; k += THREADS) s_M[k] = M[k];
    __syncthreads();

    // Step 1: FM[r][c] = sum_y F[r][y] * M[y][c]   (320 elements, strided)
    for (int k = t; k < NF; k += THREADS) {
        const int r = k >> 4, c = k & 15;
        float acc = 0.0f;
#pragma unroll
        for (int y = 0; y < FEAT_DIM; y++)
            acc = fmaf(s_F[r * FPAD + y], s_M[y * FEAT_DIM + c], acc);
        s_FM[r * FPAD + c] = acc;
    }
    __syncthreads();

    // Step 2: table entries from 4 dot products each (64 FMA).
    for (int e = t; e < TBL; e += THREADS) {
        const int i = e / NUM_AA;
        const int j = e % NUM_AA;
        float gii = 0.0f, gij = 0.0f, gji = 0.0f, gjj = 0.0f;
#pragma unroll
        for (int y = 0; y < FEAT_DIM; y++) {
            const float fiy  = s_F[i * FPAD + y];
            const float fjy  = s_F[j * FPAD + y];
            const float fmiy = s_FM[i * FPAD + y];
            const float fmjy = s_FM[j * FPAD + y];
            gii = fmaf(fmiy, fiy, gii);
            gij = fmaf(fmiy, fjy, gij);
            gji = fmaf(fmjy, fiy, gji);
            gjj = fmaf(fmjy, fjy, gjj);
        }
        s_tbl[e] = tanhf(gii - gij - gji + gjj);
    }
    __syncthreads();

    // Persistent grid-stride gather, 4 independent 128-bit lanes in flight.
    const int stride = gridDim.x * THREADS;
    int p = blockIdx.x * THREADS + t;

    for (; p + 3 * stride < n4; p += 4 * stride) {
        int4 a0 = idx_i4[p];
        int4 a1 = idx_i4[p + stride];
        int4 a2 = idx_i4[p + 2 * stride];
        int4 a3 = idx_i4[p + 3 * stride];
        int4 b0 = idx_j4[p];
        int4 b1 = idx_j4[p + stride];
        int4 b2 = idx_j4[p + 2 * stride];
        int4 b3 = idx_j4[p + 3 * stride];
        float4 o;
        o.x = s_tbl[a0.x * NUM_AA + b0.x];
        o.y = s_tbl[a0.y * NUM_AA + b0.y];
        o.z = s_tbl[a0.z * NUM_AA + b0.z];
        o.w = s_tbl[a0.w * NUM_AA + b0.w];
        out4[p] = o;
        o.x = s_tbl[a1.x * NUM_AA + b1.x];
        o.y = s_tbl[a1.y * NUM_AA + b1.y];
        o.z = s_tbl[a1.z * NUM_AA + b1.z];
        o.w = s_tbl[a1.w * NUM_AA + b1.w];
        out4[p + stride] = o;
        o.x = s_tbl[a2.x * NUM_AA + b2.x];
        o.y = s_tbl[a2.y * NUM_AA + b2.y];
        o.z = s_tbl[a2.z * NUM_AA + b2.z];
        o.w = s_tbl[a2.w * NUM_AA + b2.w];
        out4[p + 2 * stride] = o;
        o.x = s_tbl[a3.x * NUM_AA + b3.x];
        o.y = s_tbl[a3.y * NUM_AA + b3.y];
        o.z = s_tbl[a3.z * NUM_AA + b3.z];
        o.w = s_tbl[a3.w * NUM_AA + b3.w];
        out4[p + 3 * stride] = o;
    }
    for (; p < n4; p += stride) {
        int4 a = idx_i4[p];
        int4 b = idx_j4[p];
        float4 o;
        o.x = s_tbl[a.x * NUM_AA + b.x];
        o.y = s_tbl[a.y * NUM_AA + b.y];
        o.z = s_tbl[a.z * NUM_AA + b.z];
        o.w = s_tbl[a.w * NUM_AA + b.w];
        out4[p] = o;
    }
}

extern "C" void kernel_launch(void* const* d_in, const int* in_sizes, int n_in,
                              void* d_out, int out_size)
{
    const float* features = (const float*)d_in[0];   // [20,16]
    const float* M        = (const float*)d_in[1];   // [16,16]
    const int*   idx_i    = (const int*)d_in[2];     // [P]
    const int*   idx_j    = (const int*)d_in[3];     // [P]
    float*       out      = (float*)d_out;           // [P]

    const int P  = out_size;   // 8,388,608
    const int n4 = P / 4;      // 2,097,152

    // Persistent single-wave grid.
    static int blocks = 0;
    if (blocks == 0) {
        int per_sm = 0;
        cudaOccupancyMaxActiveBlocksPerMultiprocessor(
            &per_sm, snack_fused_kernel, THREADS, 0);
        if (per_sm < 1) per_sm = 1;
        int sms = 0;
        cudaDeviceGetAttribute(&sms, cudaDevAttrMultiProcessorCount, 0);
        if (sms <= 0) sms = 148;
        blocks = per_sm * sms;
        int max_blocks = (n4 + THREADS - 1) / THREADS;
        if (blocks > max_blocks) blocks = max_blocks;
    }

    snack_fused_kernel<<<blocks, THREADS>>>(
        features, M,
        (const int4*)idx_i, (const int4*)idx_j,
        (float4*)out, n4);
}